// round 2
// baseline (speedup 1.0000x reference)
#include <cuda_runtime.h>
#include <cstdint>

#define N_B 8
#define NQ  1024
#define NK  1024
#define DD  1024
#define HH  16
#define DH  64

// Scratch (device globals: allocation-free per harness rules)
__device__ float g_q[HH*N_B*NQ*DH];   // [h][n][iq][e]
__device__ float g_k[HH*N_B*NK*DH];
__device__ float g_v[HH*N_B*NK*DH];
__device__ float g_o[N_B*NQ*DD];      // [n][iq][h*64+e]

__device__ __forceinline__ uint32_t f2tf(float x) {
    uint32_t u; asm("cvt.rna.tf32.f32 %0, %1;" : "=r"(u) : "f"(x)); return u;
}

__device__ __forceinline__ void mma8(float* c, const uint32_t* a, const uint32_t* b) {
    asm volatile(
        "mma.sync.aligned.m16n8k8.row.col.f32.tf32.tf32.f32 "
        "{%0,%1,%2,%3}, {%4,%5,%6,%7}, {%8,%9}, {%0,%1,%2,%3};"
        : "+f"(c[0]), "+f"(c[1]), "+f"(c[2]), "+f"(c[3])
        : "r"(a[0]), "r"(a[1]), "r"(a[2]), "r"(a[3]), "r"(b[0]), "r"(b[1]));
}

// ---------------------------------------------------------------------------
// GEMM: C[m, r] = sum_d A[m,d] * W[r,d]   (M=8192, N=1024, K=1024, tf32 mma)
// mode 0: store to head-major layout  out[((r>>6)*8 + (m>>10))*65536 + (m&1023)*64 + (r&63)]
// mode 1: store row-major             out[m*1024 + r]
// ---------------------------------------------------------------------------
#define GPAD 20

__global__ __launch_bounds__(256) void gemm_nt(
    const float* __restrict__ A, const float* __restrict__ W,
    float* __restrict__ out, int mode)
{
    __shared__ float As[128 * GPAD];
    __shared__ float Bs[128 * GPAD];
    const int tid  = threadIdx.x;
    const int lane = tid & 31, warp = tid >> 5;
    const int wm = warp >> 2, wn = warp & 3;
    const int m0 = blockIdx.y * 128, n0 = blockIdx.x * 128;

    float c[4][4][4];
#pragma unroll
    for (int a = 0; a < 4; a++)
#pragma unroll
        for (int b = 0; b < 4; b++)
#pragma unroll
            for (int i = 0; i < 4; i++) c[a][b][i] = 0.f;

    for (int k0 = 0; k0 < DD; k0 += 16) {
#pragma unroll
        for (int i = 0; i < 2; i++) {
            int f = tid * 2 + i;           // 0..511
            int row = f >> 2, cb = (f & 3) * 4;
            float4 va = *(const float4*)(A + (size_t)(m0 + row) * DD + k0 + cb);
            As[row * GPAD + cb + 0] = __uint_as_float(f2tf(va.x));
            As[row * GPAD + cb + 1] = __uint_as_float(f2tf(va.y));
            As[row * GPAD + cb + 2] = __uint_as_float(f2tf(va.z));
            As[row * GPAD + cb + 3] = __uint_as_float(f2tf(va.w));
            float4 vb = *(const float4*)(W + (size_t)(n0 + row) * DD + k0 + cb);
            Bs[row * GPAD + cb + 0] = __uint_as_float(f2tf(vb.x));
            Bs[row * GPAD + cb + 1] = __uint_as_float(f2tf(vb.y));
            Bs[row * GPAD + cb + 2] = __uint_as_float(f2tf(vb.z));
            Bs[row * GPAD + cb + 3] = __uint_as_float(f2tf(vb.w));
        }
        __syncthreads();
#pragma unroll
        for (int kk = 0; kk < 2; kk++) {
            uint32_t af[4][4], bf[4][2];
#pragma unroll
            for (int mt = 0; mt < 4; mt++) {
                int ar = wm * 64 + mt * 16 + (lane >> 2);
                int ac = kk * 8 + (lane & 3);
                af[mt][0] = __float_as_uint(As[ar * GPAD + ac]);
                af[mt][1] = __float_as_uint(As[(ar + 8) * GPAD + ac]);
                af[mt][2] = __float_as_uint(As[ar * GPAD + ac + 4]);
                af[mt][3] = __float_as_uint(As[(ar + 8) * GPAD + ac + 4]);
            }
#pragma unroll
            for (int nt = 0; nt < 4; nt++) {
                int br = wn * 32 + nt * 8 + (lane >> 2);
                int bc = kk * 8 + (lane & 3);
                bf[nt][0] = __float_as_uint(Bs[br * GPAD + bc]);
                bf[nt][1] = __float_as_uint(Bs[br * GPAD + bc + 4]);
            }
#pragma unroll
            for (int mt = 0; mt < 4; mt++)
#pragma unroll
                for (int nt = 0; nt < 4; nt++)
                    mma8(c[mt][nt], af[mt], bf[nt]);
        }
        __syncthreads();
    }

    // store
#pragma unroll
    for (int mt = 0; mt < 4; mt++) {
        int mr = m0 + wm * 64 + mt * 16 + (lane >> 2);
#pragma unroll
        for (int nt = 0; nt < 4; nt++) {
            int nc = n0 + wn * 32 + nt * 8 + 2 * (lane & 3);
#pragma unroll
            for (int half = 0; half < 2; half++) {
                int m = mr + half * 8;
#pragma unroll
                for (int cc = 0; cc < 2; cc++) {
                    int r = nc + cc;
                    float v = c[mt][nt][half * 2 + cc];
                    if (mode == 0) {
                        size_t idx = ((size_t)((r >> 6) * N_B + (m >> 10)) << 16)
                                   + (size_t)((m & 1023) * 64 + (r & 63));
                        out[idx] = v;
                    } else {
                        out[(size_t)m * DD + r] = v;
                    }
                }
            }
        }
    }
}

// ---------------------------------------------------------------------------
// Flash-style attention with masked renormalization.
// One block = 64 q-rows of one (h,n). 4 warps, warp handles 16 rows.
// Online stats per row: m (max), Z = sum exp, S = sum exp*mask.
// Final: out = (sum exp*mask*v) / (S + EPS*Z)   == softmax*mask renormalized.
// ---------------------------------------------------------------------------
#define APAD 66
#define ATTN_SMEM (3 * 64 * APAD * (int)sizeof(float))

__global__ __launch_bounds__(128) void attn(
    const float* __restrict__ gq, const float* __restrict__ gk,
    const float* __restrict__ gv, const float* __restrict__ mask,
    float* __restrict__ go)
{
    extern __shared__ float smem[];
    float* Ks = smem;
    float* Vs = smem + 64 * APAD;
    float* Ps = smem + 2 * 64 * APAD;

    const int tid  = threadIdx.x;
    const int lane = tid & 31, warp = tid >> 5;
    const int bh = blockIdx.y;          // h*8 + n
    const int q0 = blockIdx.x * 64;
    const size_t hb = (size_t)bh * (NQ * DH);

    // Stage Q tile through Ps, pick up A-fragments into registers.
    for (int i = tid; i < 64 * 16; i += 128) {
        int row = i >> 4, cb = (i & 15) * 4;
        float4 v = *(const float4*)(gq + hb + (size_t)(q0 + row) * DH + cb);
        Ps[row * APAD + cb + 0] = __uint_as_float(f2tf(v.x));
        Ps[row * APAD + cb + 1] = __uint_as_float(f2tf(v.y));
        Ps[row * APAD + cb + 2] = __uint_as_float(f2tf(v.z));
        Ps[row * APAD + cb + 3] = __uint_as_float(f2tf(v.w));
    }
    __syncthreads();

    const int qr = warp * 16 + (lane >> 2);   // tile-local row for frag rows qr, qr+8
    uint32_t qa[8][4];
#pragma unroll
    for (int kk = 0; kk < 8; kk++) {
        int ac = kk * 8 + (lane & 3);
        qa[kk][0] = __float_as_uint(Ps[qr * APAD + ac]);
        qa[kk][1] = __float_as_uint(Ps[(qr + 8) * APAD + ac]);
        qa[kk][2] = __float_as_uint(Ps[qr * APAD + ac + 4]);
        qa[kk][3] = __float_as_uint(Ps[(qr + 8) * APAD + ac + 4]);
    }

    float o[8][4];
#pragma unroll
    for (int et = 0; et < 8; et++)
#pragma unroll
        for (int i = 0; i < 4; i++) o[et][i] = 0.f;

    float mst0 = -1e30f, mst1 = -1e30f;
    float Z0 = 0.f, Z1 = 0.f, S0 = 0.f, S1 = 0.f;

    const float* mbase = mask + (size_t)bh * ((size_t)NQ * NK)
                              + (size_t)(q0 + warp * 16 + (lane >> 2)) * NK;

    for (int kt = 0; kt < 16; kt++) {
        const int k0 = kt * 64;
        __syncthreads();   // all warps done reading Ks/Vs of previous tile
        for (int i = tid; i < 64 * 16; i += 128) {
            int row = i >> 4, cb = (i & 15) * 4;
            float4 vk = *(const float4*)(gk + hb + (size_t)(k0 + row) * DH + cb);
            Ks[row * APAD + cb + 0] = __uint_as_float(f2tf(vk.x));
            Ks[row * APAD + cb + 1] = __uint_as_float(f2tf(vk.y));
            Ks[row * APAD + cb + 2] = __uint_as_float(f2tf(vk.z));
            Ks[row * APAD + cb + 3] = __uint_as_float(f2tf(vk.w));
            float4 vv = *(const float4*)(gv + hb + (size_t)(k0 + row) * DH + cb);
            Vs[row * APAD + cb + 0] = __uint_as_float(f2tf(vv.x));
            Vs[row * APAD + cb + 1] = __uint_as_float(f2tf(vv.y));
            Vs[row * APAD + cb + 2] = __uint_as_float(f2tf(vv.z));
            Vs[row * APAD + cb + 3] = __uint_as_float(f2tf(vv.w));
        }
        __syncthreads();

        // S = Q K^T / 8   (16 q-rows x 64 keys per warp)
        float s[8][4];
#pragma unroll
        for (int nt = 0; nt < 8; nt++)
#pragma unroll
            for (int i = 0; i < 4; i++) s[nt][i] = 0.f;
#pragma unroll
        for (int kk = 0; kk < 8; kk++) {
#pragma unroll
            for (int nt = 0; nt < 8; nt++) {
                uint32_t bf[2];
                int kr = nt * 8 + (lane >> 2);
                int kc = kk * 8 + (lane & 3);
                bf[0] = __float_as_uint(Ks[kr * APAD + kc]);
                bf[1] = __float_as_uint(Ks[kr * APAD + kc + 4]);
                mma8(s[nt], qa[kk], bf);
            }
        }

        float mx0 = -1e30f, mx1 = -1e30f;
#pragma unroll
        for (int nt = 0; nt < 8; nt++) {
            s[nt][0] *= 0.125f; s[nt][1] *= 0.125f;
            s[nt][2] *= 0.125f; s[nt][3] *= 0.125f;
            mx0 = fmaxf(mx0, fmaxf(s[nt][0], s[nt][1]));
            mx1 = fmaxf(mx1, fmaxf(s[nt][2], s[nt][3]));
        }
        mx0 = fmaxf(mx0, __shfl_xor_sync(0xffffffffu, mx0, 1));
        mx0 = fmaxf(mx0, __shfl_xor_sync(0xffffffffu, mx0, 2));
        mx1 = fmaxf(mx1, __shfl_xor_sync(0xffffffffu, mx1, 1));
        mx1 = fmaxf(mx1, __shfl_xor_sync(0xffffffffu, mx1, 2));

        float nm0 = fmaxf(mst0, mx0), nm1 = fmaxf(mst1, mx1);
        float al0 = __expf(mst0 - nm0), al1 = __expf(mst1 - nm1);

        const float* mr0 = mbase + k0;
        const float* mr1 = mr0 + 8 * NK;
        float z0 = 0.f, z1 = 0.f, sm0 = 0.f, sm1 = 0.f;
#pragma unroll
        for (int nt = 0; nt < 8; nt++) {
            int cc = nt * 8 + 2 * (lane & 3);
            float p00 = __expf(s[nt][0] - nm0), p01 = __expf(s[nt][1] - nm0);
            float p10 = __expf(s[nt][2] - nm1), p11 = __expf(s[nt][3] - nm1);
            z0 += p00 + p01; z1 += p10 + p11;
            float pm00 = p00 * mr0[cc],     pm01 = p01 * mr0[cc + 1];
            float pm10 = p10 * mr1[cc],     pm11 = p11 * mr1[cc + 1];
            sm0 += pm00 + pm01; sm1 += pm10 + pm11;
            Ps[qr * APAD + cc]           = __uint_as_float(f2tf(pm00));
            Ps[qr * APAD + cc + 1]       = __uint_as_float(f2tf(pm01));
            Ps[(qr + 8) * APAD + cc]     = __uint_as_float(f2tf(pm10));
            Ps[(qr + 8) * APAD + cc + 1] = __uint_as_float(f2tf(pm11));
        }
        z0 += __shfl_xor_sync(0xffffffffu, z0, 1);  z0 += __shfl_xor_sync(0xffffffffu, z0, 2);
        z1 += __shfl_xor_sync(0xffffffffu, z1, 1);  z1 += __shfl_xor_sync(0xffffffffu, z1, 2);
        sm0 += __shfl_xor_sync(0xffffffffu, sm0, 1); sm0 += __shfl_xor_sync(0xffffffffu, sm0, 2);
        sm1 += __shfl_xor_sync(0xffffffffu, sm1, 1); sm1 += __shfl_xor_sync(0xffffffffu, sm1, 2);

        Z0 = Z0 * al0 + z0;  Z1 = Z1 * al1 + z1;
        S0 = S0 * al0 + sm0; S1 = S1 * al1 + sm1;
        mst0 = nm0; mst1 = nm1;
#pragma unroll
        for (int et = 0; et < 8; et++) {
            o[et][0] *= al0; o[et][1] *= al0;
            o[et][2] *= al1; o[et][3] *= al1;
        }
        __syncwarp();

        // O += P V   (P: 16 x 64 keys, V: 64 keys x 64 e-dims)
#pragma unroll
        for (int kk = 0; kk < 8; kk++) {
            uint32_t pa[4];
            int pc = kk * 8 + (lane & 3);
            pa[0] = __float_as_uint(Ps[qr * APAD + pc]);
            pa[1] = __float_as_uint(Ps[(qr + 8) * APAD + pc]);
            pa[2] = __float_as_uint(Ps[qr * APAD + pc + 4]);
            pa[3] = __float_as_uint(Ps[(qr + 8) * APAD + pc + 4]);
#pragma unroll
            for (int et = 0; et < 8; et++) {
                uint32_t bf[2];
                bf[0] = __float_as_uint(Vs[(kk * 8 + (lane & 3)) * APAD + et * 8 + (lane >> 2)]);
                bf[1] = __float_as_uint(Vs[(kk * 8 + (lane & 3) + 4) * APAD + et * 8 + (lane >> 2)]);
                mma8(o[et], pa, bf);
            }
        }
    }

    float d0 = 1.f / (S0 + 1e-6f * Z0);
    float d1 = 1.f / (S1 + 1e-6f * Z1);

    const int n = bh & 7, h = bh >> 3;
    float* or0 = go + (size_t)(n * NQ + q0 + warp * 16 + (lane >> 2)) * DD + h * DH;
    float* or1 = or0 + 8 * DD;
#pragma unroll
    for (int et = 0; et < 8; et++) {
        int cc = et * 8 + 2 * (lane & 3);
        or0[cc]     = o[et][0] * d0;
        or0[cc + 1] = o[et][1] * d0;
        or1[cc]     = o[et][2] * d1;
        or1[cc + 1] = o[et][3] * d1;
    }
}

// ---------------------------------------------------------------------------
extern "C" void kernel_launch(void* const* d_in, const int* in_sizes, int n_in,
                              void* d_out, int out_size)
{
    const float* q    = (const float*)d_in[0];
    const float* k    = (const float*)d_in[1];
    const float* v    = (const float*)d_in[2];
    const float* mask = (const float*)d_in[3];
    const float* Wq   = (const float*)d_in[4];
    const float* Wk   = (const float*)d_in[5];
    const float* Wv   = (const float*)d_in[6];
    const float* Wo   = (const float*)d_in[7];
    float* out = (float*)d_out;

    float *pq, *pk, *pv, *po;
    cudaGetSymbolAddress((void**)&pq, g_q);
    cudaGetSymbolAddress((void**)&pk, g_k);
    cudaGetSymbolAddress((void**)&pv, g_v);
    cudaGetSymbolAddress((void**)&po, g_o);

    cudaFuncSetAttribute(attn, cudaFuncAttributeMaxDynamicSharedMemorySize, ATTN_SMEM);

    dim3 gg(8, 64);   // N=1024/128, M=8192/128
    gemm_nt<<<gg, 256>>>(q, Wq, pq, 0);
    gemm_nt<<<gg, 256>>>(k, Wk, pk, 0);
    gemm_nt<<<gg, 256>>>(v, Wv, pv, 0);
    attn<<<dim3(16, 128), 128, ATTN_SMEM>>>(pq, pk, pv, mask, po);
    gemm_nt<<<gg, 256>>>(po, Wo, out, 1);
}

// round 3
// speedup vs baseline: 1.2027x; 1.2027x over previous
#include <cuda_runtime.h>
#include <cstdint>

#define N_B 8
#define NQ  1024
#define NK  1024
#define DD  1024
#define HH  16
#define DH  64

// Scratch (device globals: allocation-free per harness rules)
__device__ float g_q[HH*N_B*NQ*DH];   // [h][n][iq][e]
__device__ float g_k[HH*N_B*NK*DH];
__device__ float g_v[HH*N_B*NK*DH];
__device__ float g_o[N_B*NQ*DD];      // [n][iq][h*64+e]

__device__ __forceinline__ uint32_t f2tf(float x) {
    uint32_t u; asm("cvt.rna.tf32.f32 %0, %1;" : "=r"(u) : "f"(x)); return u;
}

__device__ __forceinline__ void mma8(float* c, const uint32_t* a, const uint32_t* b) {
    asm volatile(
        "mma.sync.aligned.m16n8k8.row.col.f32.tf32.tf32.f32 "
        "{%0,%1,%2,%3}, {%4,%5,%6,%7}, {%8,%9}, {%0,%1,%2,%3};"
        : "+f"(c[0]), "+f"(c[1]), "+f"(c[2]), "+f"(c[3])
        : "r"(a[0]), "r"(a[1]), "r"(a[2]), "r"(a[3]), "r"(b[0]), "r"(b[1]));
}

// ldmatrix x4 (b16 view): each 8x8 b16 matrix == 8x4 f32 tile, thread t -> (t>>2, t&3)
__device__ __forceinline__ void ldsm4(uint32_t* d, uint32_t addr) {
    asm volatile("ldmatrix.sync.aligned.m8n8.x4.shared.b16 {%0,%1,%2,%3}, [%4];"
        : "=r"(d[0]), "=r"(d[1]), "=r"(d[2]), "=r"(d[3]) : "r"(addr));
}

__device__ __forceinline__ uint32_t s2u(const void* p) {
    return (uint32_t)__cvta_generic_to_shared(p);
}

// ---------------------------------------------------------------------------
// GEMM: C[m, r] = sum_d A[m,d] * W[r,d]   (M=8192, N=1024, K=1024, tf32 mma)
// Double-buffered smem, LDSM fragments, packed STS.128 staging.
// mode 0: head-major scatter; mode 1: row-major.
// ---------------------------------------------------------------------------
#define GPAD 20   // 80B row pitch: 16B-aligned, 5 units mod 8 -> LDSM conflict-free

__global__ __launch_bounds__(256) void gemm_nt(
    const float* __restrict__ A, const float* __restrict__ W,
    float* __restrict__ out, int mode)
{
    __shared__ float As[2][128 * GPAD];
    __shared__ float Bs[2][128 * GPAD];
    const int tid  = threadIdx.x;
    const int lane = tid & 31, warp = tid >> 5;
    const int wm = warp >> 2, wn = warp & 3;
    const int m0 = blockIdx.y * 128, n0 = blockIdx.x * 128;

    // staging coords: this thread stages rows f=2*tid, 2*tid+1 (f>>2 row, (f&3)*4 col)
    const int sr0 = (2 * tid) >> 2,     sc0 = ((2 * tid) & 3) * 4;
    const int sr1 = (2 * tid + 1) >> 2, sc1 = ((2 * tid + 1) & 3) * 4;

    float c[4][4][4];
#pragma unroll
    for (int a = 0; a < 4; a++)
#pragma unroll
        for (int b = 0; b < 4; b++)
#pragma unroll
            for (int i = 0; i < 4; i++) c[a][b][i] = 0.f;

    // fragment LDSM base offsets (in floats)
    const int a_off = (wm * 64 + (lane & 15)) * GPAD + 4 * (lane >> 4);
    const int b_off = (wn * 32 + ((lane >> 4) * 8) + (lane & 7)) * GPAD + 4 * ((lane >> 3) & 1);

    // prologue: stage k0=0 into buffer 0
    {
        float4 va0 = *(const float4*)(A + (size_t)(m0 + sr0) * DD + sc0);
        float4 va1 = *(const float4*)(A + (size_t)(m0 + sr1) * DD + sc1);
        float4 vb0 = *(const float4*)(W + (size_t)(n0 + sr0) * DD + sc0);
        float4 vb1 = *(const float4*)(W + (size_t)(n0 + sr1) * DD + sc1);
        *(uint4*)(As[0] + sr0 * GPAD + sc0) = make_uint4(f2tf(va0.x), f2tf(va0.y), f2tf(va0.z), f2tf(va0.w));
        *(uint4*)(As[0] + sr1 * GPAD + sc1) = make_uint4(f2tf(va1.x), f2tf(va1.y), f2tf(va1.z), f2tf(va1.w));
        *(uint4*)(Bs[0] + sr0 * GPAD + sc0) = make_uint4(f2tf(vb0.x), f2tf(vb0.y), f2tf(vb0.z), f2tf(vb0.w));
        *(uint4*)(Bs[0] + sr1 * GPAD + sc1) = make_uint4(f2tf(vb1.x), f2tf(vb1.y), f2tf(vb1.z), f2tf(vb1.w));
    }
    __syncthreads();

    for (int k0 = 0; k0 < DD; k0 += 16) {
        const int buf = (k0 >> 4) & 1;
        const bool has_next = (k0 + 16) < DD;
        float4 na0, na1, nb0, nb1;
        if (has_next) {
            const int kn = k0 + 16;
            na0 = *(const float4*)(A + (size_t)(m0 + sr0) * DD + kn + sc0);
            na1 = *(const float4*)(A + (size_t)(m0 + sr1) * DD + kn + sc1);
            nb0 = *(const float4*)(W + (size_t)(n0 + sr0) * DD + kn + sc0);
            nb1 = *(const float4*)(W + (size_t)(n0 + sr1) * DD + kn + sc1);
        }

#pragma unroll
        for (int kk = 0; kk < 2; kk++) {
            uint32_t af[4][4], bf[4][4];
#pragma unroll
            for (int mt = 0; mt < 4; mt++)
                ldsm4(af[mt], s2u(As[buf] + a_off + mt * 16 * GPAD + kk * 8));
#pragma unroll
            for (int ntp = 0; ntp < 2; ntp++)
                ldsm4(bf[ntp], s2u(Bs[buf] + b_off + ntp * 16 * GPAD + kk * 8));
#pragma unroll
            for (int mt = 0; mt < 4; mt++)
#pragma unroll
                for (int ntp = 0; ntp < 2; ntp++) {
                    mma8(c[mt][ntp * 2 + 0], af[mt], &bf[ntp][0]);
                    mma8(c[mt][ntp * 2 + 1], af[mt], &bf[ntp][2]);
                }
        }

        if (has_next) {
            float* Ad = As[buf ^ 1];
            float* Bd = Bs[buf ^ 1];
            *(uint4*)(Ad + sr0 * GPAD + sc0) = make_uint4(f2tf(na0.x), f2tf(na0.y), f2tf(na0.z), f2tf(na0.w));
            *(uint4*)(Ad + sr1 * GPAD + sc1) = make_uint4(f2tf(na1.x), f2tf(na1.y), f2tf(na1.z), f2tf(na1.w));
            *(uint4*)(Bd + sr0 * GPAD + sc0) = make_uint4(f2tf(nb0.x), f2tf(nb0.y), f2tf(nb0.z), f2tf(nb0.w));
            *(uint4*)(Bd + sr1 * GPAD + sc1) = make_uint4(f2tf(nb1.x), f2tf(nb1.y), f2tf(nb1.z), f2tf(nb1.w));
        }
        __syncthreads();
    }

    // store
#pragma unroll
    for (int mt = 0; mt < 4; mt++) {
        int mr = m0 + wm * 64 + mt * 16 + (lane >> 2);
#pragma unroll
        for (int nt = 0; nt < 4; nt++) {
            int nc = n0 + wn * 32 + nt * 8 + 2 * (lane & 3);
#pragma unroll
            for (int half = 0; half < 2; half++) {
                int m = mr + half * 8;
#pragma unroll
                for (int cc = 0; cc < 2; cc++) {
                    int r = nc + cc;
                    float v = c[mt][nt][half * 2 + cc];
                    if (mode == 0) {
                        size_t idx = ((size_t)((r >> 6) * N_B + (m >> 10)) << 16)
                                   + (size_t)((m & 1023) * 64 + (r & 63));
                        out[idx] = v;
                    } else {
                        out[(size_t)m * DD + r] = v;
                    }
                }
            }
        }
    }
}

// ---------------------------------------------------------------------------
// Flash-style attention with masked renormalization.
// One block = 64 q-rows of one (h,n). 4 warps, warp handles 16 rows.
// LDSM fragment loads; P kept in registers (permuted-V trick); V stored
// transposed + column-permuted (even keys -> cols 0-3, odd -> cols 4-7 of
// each 8-group) so the S-mma C-fragment is directly a valid A-fragment.
// ---------------------------------------------------------------------------
#define APAD 68   // 272B row pitch: 16B-aligned, 17 units mod 8 = 1 -> LDSM conflict-free

__global__ __launch_bounds__(128) void attn(
    const float* __restrict__ gq, const float* __restrict__ gk,
    const float* __restrict__ gv, const float* __restrict__ mask,
    float* __restrict__ go)
{
    __shared__ float Ks[64 * APAD];
    __shared__ float Vt[64 * APAD];   // Vt[e][perm(key)]

    const int tid  = threadIdx.x;
    const int lane = tid & 31, warp = tid >> 5;
    const int bh = blockIdx.y;          // h*8 + n
    const int q0 = blockIdx.x * 64;
    const size_t hb = (size_t)bh * (NQ * DH);

    // --- stage Q through Ks, load A-fragments via LDSM ---
    for (int i = tid; i < 64 * 16; i += 128) {
        int row = i >> 4, cb = (i & 15) * 4;
        float4 v = *(const float4*)(gq + hb + (size_t)(q0 + row) * DH + cb);
        *(uint4*)(Ks + row * APAD + cb) = make_uint4(f2tf(v.x), f2tf(v.y), f2tf(v.z), f2tf(v.w));
    }
    __syncthreads();

    uint32_t qa[8][4];
    {
        const int q_off = (warp * 16 + (lane & 15)) * APAD + 4 * (lane >> 4);
#pragma unroll
        for (int kk = 0; kk < 8; kk++)
            ldsm4(qa[kk], s2u(Ks + q_off + kk * 8));
    }
    __syncthreads();

    float o[8][4];
#pragma unroll
    for (int et = 0; et < 8; et++)
#pragma unroll
        for (int i = 0; i < 4; i++) o[et][i] = 0.f;

    float mst0 = -1e30f, mst1 = -1e30f;
    float Z0 = 0.f, Z1 = 0.f, S0 = 0.f, S1 = 0.f;

    const float* mbase = mask + (size_t)bh * ((size_t)NQ * NK)
                              + (size_t)(q0 + warp * 16 + (lane >> 2)) * NK;

    // fragment LDSM offsets
    const int kb_off = ((lane >> 4) * 8 + (lane & 7)) * APAD + 4 * ((lane >> 3) & 1);
    const int vb_off = kb_off;  // same lane pattern, different array

    for (int kt = 0; kt < 16; kt++) {
        const int k0 = kt * 64;
        __syncthreads();   // all warps done reading Ks/Vt of previous tile

        // stage K (row-major, tf32)
        for (int i = tid; i < 64 * 16; i += 128) {
            int row = i >> 4, cb = (i & 15) * 4;
            float4 vk = *(const float4*)(gk + hb + (size_t)(k0 + row) * DH + cb);
            *(uint4*)(Ks + row * APAD + cb) = make_uint4(f2tf(vk.x), f2tf(vk.y), f2tf(vk.z), f2tf(vk.w));
        }
        // stage V transposed + column-permuted
        for (int i = tid; i < 64 * 16; i += 128) {
            int key = (i & 7) | (((i >> 5) & 7) << 3);
            int cb4 = ((i >> 3) & 3) | (((i >> 8) & 3) << 2);
            int e0  = cb4 * 4;
            float4 vv = *(const float4*)(gv + hb + (size_t)(k0 + key) * DH + e0);
            int lk = key & 7;
            int pc = (key & ~7) + ((lk & 1) ? 4 + (lk >> 1) : (lk >> 1));
            Vt[(e0 + 0) * APAD + pc] = __uint_as_float(f2tf(vv.x));
            Vt[(e0 + 1) * APAD + pc] = __uint_as_float(f2tf(vv.y));
            Vt[(e0 + 2) * APAD + pc] = __uint_as_float(f2tf(vv.z));
            Vt[(e0 + 3) * APAD + pc] = __uint_as_float(f2tf(vv.w));
        }
        __syncthreads();

        // S = Q K^T / 8   (16 q-rows x 64 keys per warp)
        float s[8][4];
#pragma unroll
        for (int nt = 0; nt < 8; nt++)
#pragma unroll
            for (int i = 0; i < 4; i++) s[nt][i] = 0.f;
#pragma unroll
        for (int kk = 0; kk < 8; kk++) {
#pragma unroll
            for (int ntp = 0; ntp < 4; ntp++) {
                uint32_t bf[4];
                ldsm4(bf, s2u(Ks + kb_off + ntp * 16 * APAD + kk * 8));
                mma8(s[ntp * 2 + 0], qa[kk], &bf[0]);
                mma8(s[ntp * 2 + 1], qa[kk], &bf[2]);
            }
        }

        float mx0 = -1e30f, mx1 = -1e30f;
#pragma unroll
        for (int nt = 0; nt < 8; nt++) {
            s[nt][0] *= 0.125f; s[nt][1] *= 0.125f;
            s[nt][2] *= 0.125f; s[nt][3] *= 0.125f;
            mx0 = fmaxf(mx0, fmaxf(s[nt][0], s[nt][1]));
            mx1 = fmaxf(mx1, fmaxf(s[nt][2], s[nt][3]));
        }
        mx0 = fmaxf(mx0, __shfl_xor_sync(0xffffffffu, mx0, 1));
        mx0 = fmaxf(mx0, __shfl_xor_sync(0xffffffffu, mx0, 2));
        mx1 = fmaxf(mx1, __shfl_xor_sync(0xffffffffu, mx1, 1));
        mx1 = fmaxf(mx1, __shfl_xor_sync(0xffffffffu, mx1, 2));

        float nm0 = fmaxf(mst0, mx0), nm1 = fmaxf(mst1, mx1);
        float al0 = __expf(mst0 - nm0), al1 = __expf(mst1 - nm1);

        const float* mr0 = mbase + k0;
        const float* mr1 = mr0 + 8 * NK;
        float z0 = 0.f, z1 = 0.f, sm0 = 0.f, sm1 = 0.f;
#pragma unroll
        for (int nt = 0; nt < 8; nt++) {
            int cc = nt * 8 + 2 * (lane & 3);
            float p00 = __expf(s[nt][0] - nm0), p01 = __expf(s[nt][1] - nm0);
            float p10 = __expf(s[nt][2] - nm1), p11 = __expf(s[nt][3] - nm1);
            z0 += p00 + p01; z1 += p10 + p11;
            float pm00 = p00 * mr0[cc],     pm01 = p01 * mr0[cc + 1];
            float pm10 = p10 * mr1[cc],     pm11 = p11 * mr1[cc + 1];
            sm0 += pm00 + pm01; sm1 += pm10 + pm11;
            // keep P in registers as tf32 (C-fragment == permuted A-fragment)
            s[nt][0] = __uint_as_float(f2tf(pm00));
            s[nt][1] = __uint_as_float(f2tf(pm01));
            s[nt][2] = __uint_as_float(f2tf(pm10));
            s[nt][3] = __uint_as_float(f2tf(pm11));
        }
        z0 += __shfl_xor_sync(0xffffffffu, z0, 1);  z0 += __shfl_xor_sync(0xffffffffu, z0, 2);
        z1 += __shfl_xor_sync(0xffffffffu, z1, 1);  z1 += __shfl_xor_sync(0xffffffffu, z1, 2);
        sm0 += __shfl_xor_sync(0xffffffffu, sm0, 1); sm0 += __shfl_xor_sync(0xffffffffu, sm0, 2);
        sm1 += __shfl_xor_sync(0xffffffffu, sm1, 1); sm1 += __shfl_xor_sync(0xffffffffu, sm1, 2);

        Z0 = Z0 * al0 + z0;  Z1 = Z1 * al1 + z1;
        S0 = S0 * al0 + sm0; S1 = S1 * al1 + sm1;
        mst0 = nm0; mst1 = nm1;
#pragma unroll
        for (int et = 0; et < 8; et++) {
            o[et][0] *= al0; o[et][1] *= al0;
            o[et][2] *= al1; o[et][3] *= al1;
        }

        // O += P V   (P from registers; V fragments via LDSM on permuted Vt)
#pragma unroll
        for (int kk = 0; kk < 8; kk++) {
            uint32_t pa[4];
            pa[0] = __float_as_uint(s[kk][0]);
            pa[1] = __float_as_uint(s[kk][2]);
            pa[2] = __float_as_uint(s[kk][1]);
            pa[3] = __float_as_uint(s[kk][3]);
#pragma unroll
            for (int etp = 0; etp < 4; etp++) {
                uint32_t bf[4];
                ldsm4(bf, s2u(Vt + vb_off + etp * 16 * APAD + kk * 8));
                mma8(o[etp * 2 + 0], pa, &bf[0]);
                mma8(o[etp * 2 + 1], pa, &bf[2]);
            }
        }
    }

    float d0 = 1.f / (S0 + 1e-6f * Z0);
    float d1 = 1.f / (S1 + 1e-6f * Z1);

    const int n = bh & 7, h = bh >> 3;
    float* or0 = go + (size_t)(n * NQ + q0 + warp * 16 + (lane >> 2)) * DD + h * DH;
    float* or1 = or0 + 8 * DD;
#pragma unroll
    for (int et = 0; et < 8; et++) {
        int cc = et * 8 + 2 * (lane & 3);
        or0[cc]     = o[et][0] * d0;
        or0[cc + 1] = o[et][1] * d0;
        or1[cc]     = o[et][2] * d1;
        or1[cc + 1] = o[et][3] * d1;
    }
}

// ---------------------------------------------------------------------------
extern "C" void kernel_launch(void* const* d_in, const int* in_sizes, int n_in,
                              void* d_out, int out_size)
{
    const float* q    = (const float*)d_in[0];
    const float* k    = (const float*)d_in[1];
    const float* v    = (const float*)d_in[2];
    const float* mask = (const float*)d_in[3];
    const float* Wq   = (const float*)d_in[4];
    const float* Wk   = (const float*)d_in[5];
    const float* Wv   = (const float*)d_in[6];
    const float* Wo   = (const float*)d_in[7];
    float* out = (float*)d_out;

    float *pq, *pk, *pv, *po;
    cudaGetSymbolAddress((void**)&pq, g_q);
    cudaGetSymbolAddress((void**)&pk, g_k);
    cudaGetSymbolAddress((void**)&pv, g_v);
    cudaGetSymbolAddress((void**)&po, g_o);

    dim3 gg(8, 64);   // N=1024/128, M=8192/128
    gemm_nt<<<gg, 256>>>(q, Wq, pq, 0);
    gemm_nt<<<gg, 256>>>(k, Wk, pk, 0);
    gemm_nt<<<gg, 256>>>(v, Wv, pv, 0);
    attn<<<dim3(16, 128), 128>>>(pq, pk, pv, mask, po);
    gemm_nt<<<gg, 256>>>(po, Wo, out, 1);
}